// round 6
// baseline (speedup 1.0000x reference)
#include <cuda_runtime.h>
#include <math.h>

#define ND 4096
#define MM 8192
#define DE 256
#define TOPK 8

#define OBJ_THR   0.3f
#define INIT_THR  0.7f
#define MATCH_THR 0.5f
#define IOU_BACK  0.3f
#define IOU_CLASS 0.7f

#define BM 128
#define BN 128
#define BK 16
#define NSEG (ND / BM)   // 32 block-rows max

// ---------------- scratch (device globals; no allocation allowed) ----------
static __device__ float    g_feats[(size_t)ND * MM];   // compacted rows [NV, MM]
static __device__ int      g_order[ND];
static __device__ float    g_scores_s[ND];
static __device__ int      g_cls_s[ND];
static __device__ float4   g_boxes_s[ND];
static __device__ float    g_area_s[ND];
static __device__ float    g_emb_s[ND * DE];
static __device__ float    g_embc[ND * DE];            // compacted embeddings
static __device__ int      g_bad[ND];
static __device__ int      g_valid[ND];
static __device__ int      g_vpos[ND];                 // sorted row -> compact row
static __device__ int      g_nvalid;
static __device__ unsigned g_rowmaxU[ND];              // encoded fp32 max (compact idx)
static __device__ float2   g_colpart[NSEG][MM];        // per-blockrow (max, sumexp)
static __device__ float2   g_colstat[MM];              // (colmax, 1/colsum)
static __device__ float    g_topv[ND][TOPK];
static __device__ int      g_topi[ND][TOPK];
static __device__ int      g_ids[ND];

__device__ __forceinline__ unsigned encf(float f) {
    unsigned u = __float_as_uint(f);
    return (u & 0x80000000u) ? ~u : (u | 0x80000000u);
}
__device__ __forceinline__ float decf(unsigned u) {
    return (u & 0x80000000u) ? __uint_as_float(u & 0x7FFFFFFFu)
                             : __uint_as_float(~u);
}

// ---------------- 0. zero per-call state ------------------------------------
__global__ void init_kernel() {
    int i = blockIdx.x * 256 + threadIdx.x;
    if (i < ND) g_rowmaxU[i] = 0u;
}

// ---------------- 1. argsort(-scores) stable --------------------------------
__global__ void sort_kernel(const float* __restrict__ scores) {
    __shared__ unsigned long long keys[ND];
    int t = threadIdx.x;
    for (int i = t; i < ND; i += 1024) {
        unsigned u = __float_as_uint(scores[i]);
        u ^= (u & 0x80000000u) ? 0xFFFFFFFFu : 0x80000000u;
        u = ~u;                                              // descending score
        keys[i] = ((unsigned long long)u << 32) | (unsigned)i;
    }
    __syncthreads();
    for (int k = 2; k <= ND; k <<= 1) {
        for (int j = k >> 1; j > 0; j >>= 1) {
            for (int i = t; i < ND; i += 1024) {
                int ixj = i ^ j;
                if (ixj > i) {
                    bool up = ((i & k) == 0);
                    unsigned long long a = keys[i], b = keys[ixj];
                    bool sw = up ? (a > b) : (a < b);
                    if (sw) { keys[i] = b; keys[ixj] = a; }
                }
            }
            __syncthreads();
        }
    }
    for (int i = t; i < ND; i += 1024)
        g_order[i] = (int)(keys[i] & 0xFFFFFFFFu);
}

// ---------------- 2. gather sorted views (+ areas) ---------------------------
__global__ void gather_kernel(const float* __restrict__ det,
                              const float* __restrict__ scores,
                              const int*   __restrict__ cls,
                              const float* __restrict__ emb) {
    int i = blockIdx.x;
    int o = g_order[i];
    if (threadIdx.x == 0) {
        g_scores_s[i] = scores[o];
        g_cls_s[i]    = cls[o];
        float4 b;
        b.x = det[o * 4 + 0]; b.y = det[o * 4 + 1];
        b.z = det[o * 4 + 2]; b.w = det[o * 4 + 3];
        g_boxes_s[i] = b;
        g_area_s[i] = fmaxf(b.z - b.x, 0.f) * fmaxf(b.w - b.y, 0.f);
    }
    for (int k = threadIdx.x; k < DE; k += blockDim.x)
        g_emb_s[i * DE + k] = emb[o * DE + k];
}

// ---------------- 3. NMS: warp per detection, 128 j's per ballot ------------
__global__ void nms_kernel() {
    int i = (blockIdx.x * blockDim.x + threadIdx.x) >> 5;   // 4096 warps
    int lane = threadIdx.x & 31;
    float4 bx = g_boxes_s[i];
    float  si = g_scores_s[i];
    float  thr = (si < OBJ_THR) ? IOU_BACK : IOU_CLASS;
    float  area_i = g_area_s[i];
    bool bad = false;
    for (int j0 = 0; j0 < i; j0 += 128) {
        bool ex = false;
#pragma unroll
        for (int u = 0; u < 4; u++) {
            int j = j0 + u * 32 + lane;
            if (j < i) {
                float4 bb = g_boxes_s[j];
                float  aj = g_area_s[j];
                float lx = fmaxf(bx.x, bb.x), ly = fmaxf(bx.y, bb.y);
                float rx = fminf(bx.z, bb.z), ry = fminf(bx.w, bb.w);
                float w = fmaxf(rx - lx, 0.f), h = fmaxf(ry - ly, 0.f);
                float inter = w * h;
                float denom = fmaxf(area_i + aj - inter, 1e-6f);
                ex |= (inter / denom > thr);   // exact division (reference semantics)
            }
        }
        if (__any_sync(0xFFFFFFFFu, ex)) { bad = true; break; }
    }
    if (lane == 0) g_bad[i] = bad ? 1 : 0;
}

// ---------------- 4. compaction (prefix sum over valid) ---------------------
__global__ void compact_kernel() {
    __shared__ int s[1024];
    int t = threadIdx.x;
    int v[4], cnt = 0;
#pragma unroll
    for (int k = 0; k < 4; k++) {
        v[k] = g_bad[t * 4 + k] ? 0 : 1;
        cnt += v[k];
    }
    s[t] = cnt;
    __syncthreads();
    for (int off = 1; off < 1024; off <<= 1) {
        int val = s[t];
        if (t >= off) val += s[t - off];
        __syncthreads();
        s[t] = val;
        __syncthreads();
    }
    int base = s[t] - cnt;
#pragma unroll
    for (int k = 0; k < 4; k++) {
        int i = t * 4 + k;
        g_valid[i] = v[k];
        g_vpos[i] = base;
        if (v[k]) base++;
    }
    if (t == 1023) g_nvalid = s[1023];
}

__global__ void embcompact_kernel() {
    int r = blockIdx.x;
    if (!g_valid[r]) return;
    int p = g_vpos[r];
    const float4* src = (const float4*)&g_emb_s[r * DE];
    float4* dst = (float4*)&g_embc[p * DE];
    dst[threadIdx.x] = src[threadIdx.x];   // 64 threads x float4 = 256 floats
}

// ------- 5. SGEMM on compacted rows + rowmax + column-softmax partials ------
__global__ void sgemm_kernel(const float* __restrict__ B) {
    int nv = g_nvalid;
    int bm = blockIdx.y * BM;
    if (bm >= nv) return;
    __shared__ float As[BK][BM + 4];
    __shared__ float Bs[BK][BN + 4];
    __shared__ unsigned s_rmax[BM], s_cmax[BN];
    __shared__ float s_part[16][BN];      // per-threadrow column partial sums
    int bn = blockIdx.x * BN;
    int tid = threadIdx.x;   // 256
    int ti = tid / 16;       // 0..15 thread-row group
    int tr = ti * 8;
    int tc = (tid % 16) * 8;
    if (tid < BM) { s_rmax[tid] = 0u; s_cmax[tid] = 0u; }

    float acc[8][8];
#pragma unroll
    for (int i = 0; i < 8; i++)
#pragma unroll
        for (int j = 0; j < 8; j++) acc[i][j] = 0.f;

    int lrow = tid / 4;
    int lc4  = (tid % 4) * 4;

    for (int k0 = 0; k0 < DE; k0 += BK) {
        __syncthreads();
#pragma unroll
        for (int l = 0; l < 2; l++) {
            int row = l * 64 + lrow;
            float4 va = *(const float4*)&g_embc[(bm + row) * DE + k0 + lc4];
            As[lc4 + 0][row] = va.x; As[lc4 + 1][row] = va.y;
            As[lc4 + 2][row] = va.z; As[lc4 + 3][row] = va.w;
            float4 vb = *(const float4*)&B[(size_t)(bn + row) * DE + k0 + lc4];
            Bs[lc4 + 0][row] = vb.x; Bs[lc4 + 1][row] = vb.y;
            Bs[lc4 + 2][row] = vb.z; Bs[lc4 + 3][row] = vb.w;
        }
        __syncthreads();
#pragma unroll
        for (int kk = 0; kk < BK; kk++) {
            float a[8], b[8];
#pragma unroll
            for (int i = 0; i < 8; i++) a[i] = As[kk][tr + i];
#pragma unroll
            for (int j = 0; j < 8; j++) b[j] = Bs[kk][tc + j];
#pragma unroll
            for (int i = 0; i < 8; i++)
#pragma unroll
                for (int j = 0; j < 8; j++) acc[i][j] = fmaf(a[i], b[j], acc[i][j]);
        }
    }
    // write feats
#pragma unroll
    for (int i = 0; i < 8; i++) {
        float* dst = &g_feats[(size_t)(bm + tr + i) * MM + bn + tc];
        *(float4*)dst       = make_float4(acc[i][0], acc[i][1], acc[i][2], acc[i][3]);
        *(float4*)(dst + 4) = make_float4(acc[i][4], acc[i][5], acc[i][6], acc[i][7]);
    }
    // row max epilogue
#pragma unroll
    for (int i = 0; i < 8; i++) {
        if (bm + tr + i < nv) {
            float rm = acc[i][0];
#pragma unroll
            for (int j = 1; j < 8; j++) rm = fmaxf(rm, acc[i][j]);
            atomicMax(&s_rmax[tr + i], encf(rm));
        }
    }
    // block-local column max
#pragma unroll
    for (int j = 0; j < 8; j++) {
        float cm = -INFINITY;
        bool any = false;
#pragma unroll
        for (int i = 0; i < 8; i++) {
            if (bm + tr + i < nv) { cm = fmaxf(cm, acc[i][j]); any = true; }
        }
        if (any) atomicMax(&s_cmax[tc + j], encf(cm));
    }
    __syncthreads();
    // per-thread column partial sums of exp(x - blockcolmax)
#pragma unroll
    for (int j = 0; j < 8; j++) {
        float cm = decf(s_cmax[tc + j]);
        float ps = 0.f;
#pragma unroll
        for (int i = 0; i < 8; i++) {
            if (bm + tr + i < nv) ps += __expf(acc[i][j] - cm);
        }
        s_part[ti][tc + j] = ps;
    }
    if (tid < BM && bm + tid < nv) atomicMax(&g_rowmaxU[bm + tid], s_rmax[tid]);
    __syncthreads();
    // deterministic 16-way reduce per column; write (blockmax, partialsum)
    if (tid < BN) {
        float s = 0.f;
#pragma unroll
        for (int k = 0; k < 16; k++) s += s_part[k][tid];
        g_colpart[blockIdx.y][bn + tid] = make_float2(decf(s_cmax[tid]), s);
    }
}

// ---------------- 6. merge column partials (online softmax combine) ---------
__global__ void colmerge_kernel() {
    int c = blockIdx.x * 256 + threadIdx.x;
    int nseg = (g_nvalid + BM - 1) / BM;
    float m = -INFINITY, s = 0.f;
    for (int seg = 0; seg < nseg; seg++) {
        float2 p = g_colpart[seg][c];
        if (p.x > m) { s = s * __expf(m - p.x) + p.y; m = p.x; }
        else         s += p.y * __expf(p.x - m);
    }
    g_colstat[c] = make_float2(m, 1.f / s);
}

// ---------------- 7. sims + row softmax + top-8 ------------------------------
__global__ void simsrow_kernel(const int* __restrict__ memo_cls,
                               float* __restrict__ out) {
    __shared__ float srow[MM];
    __shared__ float s_red[256];
    __shared__ int   s_ri[256];
    int r = blockIdx.x, t = threadIdx.x;
    float* orow = out + 2 * ND + (size_t)r * MM;
    if (!g_valid[r]) {
        float4 z = make_float4(0.f, 0.f, 0.f, 0.f);
        float4* o4 = (float4*)orow;
        for (int j = t; j < MM / 4; j += 256) o4[j] = z;
        if (t < TOPK) { g_topv[r][t] = 0.f; g_topi[r][t] = 0; }
        return;
    }
    int v = g_vpos[r];
    float rmax = decf(g_rowmaxU[v]);
    const float4* f4 = (const float4*)(g_feats + (size_t)v * MM);
    float p0 = 0.f, p1 = 0.f;
#pragma unroll
    for (int it = 0; it < 8; it++) {
        int idx = t + it * 256;
        float4 x = f4[idx];
        ((float4*)srow)[idx] = x;
        p0 += __expf(x.x - rmax) + __expf(x.z - rmax);
        p1 += __expf(x.y - rmax) + __expf(x.w - rmax);
    }
    s_red[t] = p0 + p1;
    __syncthreads();
    for (int o = 128; o; o >>= 1) {
        if (t < o) s_red[t] += s_red[t + o];
        __syncthreads();
    }
    float rinv = 1.f / s_red[0];
    int clsr = g_cls_s[r];
    __syncthreads();
    for (int j = t; j < MM; j += 256) {
        float f = srow[j];
        float d2t = __expf(f - rmax) * rinv;
        float2 cs = g_colstat[j];
        float t2d = __expf(f - cs.x) * cs.y;
        float vs = (memo_cls[j] == clsr) ? 0.5f * (d2t + t2d) : 0.f;
        srow[j] = vs;
        orow[j] = vs;
    }
    __syncthreads();
    for (int k = 0; k < TOPK; k++) {
        float bv = -1.f; int bi = MM;
        for (int j = t; j < MM; j += 256) {
            float x = srow[j];
            if (x > bv) { bv = x; bi = j; }
        }
        s_red[t] = bv; s_ri[t] = bi;
        __syncthreads();
        for (int o = 128; o; o >>= 1) {
            if (t < o) {
                float ov = s_red[t + o]; int oi = s_ri[t + o];
                if (ov > s_red[t] || (ov == s_red[t] && oi < s_ri[t])) {
                    s_red[t] = ov; s_ri[t] = oi;
                }
            }
            __syncthreads();
        }
        if (t == 0) {
            g_topv[r][k] = s_red[0];
            g_topi[r][k] = s_ri[0];
            srow[s_ri[0]] = -2.f;
        }
        __syncthreads();
    }
}

// ---------------- 8. sequential greedy + new tracks + scatter ---------------
__global__ void greedy_kernel(const int* __restrict__ memo_track,
                              const int* __restrict__ num_tracks_ptr,
                              float* __restrict__ out) {
    __shared__ float          s_tv[ND];          // 16 KB
    __shared__ unsigned short s_pk[ND];          // 8 KB: ti|valid<<13|strong<<14|init<<15
    __shared__ unsigned       tk[MM / 32];       // taken bitmask 1 KB
    int lane = threadIdx.x;
    for (int i = lane; i < MM / 32; i += 32) tk[i] = 0u;
    for (int i = lane; i < ND; i += 32) {
        float tv = g_topv[i][0];
        int   ti = g_topi[i][0];
        float sc = g_scores_s[i];
        int   vl = g_valid[i];
        s_tv[i] = tv;
        s_pk[i] = (unsigned short)(ti | (vl << 13) |
                                   ((sc > OBJ_THR) << 14) | ((sc > INIT_THR) << 15));
    }
    __syncwarp();

    const float* sims = out + 2 * ND;

    for (int c = 0; c < ND / 32; c++) {
        int r = c * 32 + lane;
        float tv = s_tv[r];
        int pk = s_pk[r];
        int ti = pk & 0x1FFF;
        bool strong = (pk >> 14) & 1;

        bool relevant = tv > MATCH_THR;
        unsigned relmask = __ballot_sync(0xFFFFFFFFu, relevant);
        bool hazard = relevant && ((tk[ti >> 5] >> (ti & 31)) & 1u);
        unsigned same = __match_any_sync(0xFFFFFFFFu, ti);
        bool dup = relevant && ((same & relmask) != (1u << lane));
        bool anyhaz = __any_sync(0xFFFFFFFFu, hazard);
        bool anydup = __any_sync(0xFFFFFFFFu, dup);

        if (!anyhaz && !anydup) {
            int idv = -1;
            bool assign = false;
            if (relevant) {
                int cur = memo_track[ti];
                bool is_track = cur > -1;
                assign = is_track && strong;
                idv = assign ? cur : ((!is_track) ? -2 : -1);
            }
            g_ids[r] = idv;
            if (assign) atomicOr(&tk[ti >> 5], 1u << (ti & 31));
            __syncwarp();
        } else {
            for (int l = 0; l < 32; l++) {
                int rr = c * 32 + l;
                float tv0 = s_tv[rr];
                if (!(tv0 > MATCH_THR)) {
                    if (lane == 0) g_ids[rr] = -1;
                    __syncwarp();
                    continue;
                }
                float conf; int ind;
                bool ok = false;
                if (lane < TOPK) {
                    int cc = g_topi[rr][lane];
                    ok = !((tk[cc >> 5] >> (cc & 31)) & 1u);
                }
                unsigned b = __ballot_sync(0xFFFFFFFFu, ok);
                if (b) {
                    int k = __ffs(b) - 1;
                    conf = g_topv[rr][k];
                    ind  = g_topi[rr][k];
                } else {
                    const float* row = sims + (size_t)rr * MM;
                    float bv = -1.f; int bi = MM;
                    for (int j = lane; j < MM; j += 32) {
                        bool tkn = (tk[j >> 5] >> (j & 31)) & 1u;
                        float x = tkn ? 0.f : row[j];
                        if (x > bv) { bv = x; bi = j; }
                    }
                    for (int off = 16; off; off >>= 1) {
                        float ov = __shfl_down_sync(0xFFFFFFFFu, bv, off);
                        int   oi = __shfl_down_sync(0xFFFFFFFFu, bi, off);
                        if (ov > bv || (ov == bv && oi < bi)) { bv = ov; bi = oi; }
                    }
                    conf = __shfl_sync(0xFFFFFFFFu, bv, 0);
                    ind  = __shfl_sync(0xFFFFFFFFu, bi, 0);
                }
                if (lane == 0) {
                    int cur = memo_track[ind];
                    bool match = conf > MATCH_THR;
                    bool is_track = cur > -1;
                    bool strong2 = (s_pk[rr] >> 14) & 1;
                    bool assign = match && is_track && strong2;
                    g_ids[rr] = assign ? cur : ((match && !is_track) ? -2 : -1);
                    if (assign) atomicOr(&tk[ind >> 5], 1u << (ind & 31));
                }
                __syncwarp();
            }
        }
    }
    __syncwarp();

    int num_tracks = *num_tracks_ptr;
    int carry = 0;
    for (int c = 0; c < ND / 32; c++) {
        int r = c * 32 + lane;
        int idv = g_ids[r];
        int pk = s_pk[r];
        int vld = (pk >> 13) & 1;
        bool newt = (idv == -1) && ((pk >> 15) & 1) && vld;
        unsigned bm = __ballot_sync(0xFFFFFFFFu, newt);
        int rank = __popc(bm & ((1u << lane) - 1u));
        if (newt) idv = num_tracks + carry + rank;
        carry += __popc(bm);
        int o = g_order[r];
        out[o] = (float)idv;
        out[ND + o] = vld ? 1.f : 0.f;
    }
}

// ---------------- launch -----------------------------------------------------
extern "C" void kernel_launch(void* const* d_in, const int* in_sizes, int n_in,
                              void* d_out, int out_size) {
    (void)in_sizes; (void)n_in; (void)out_size;
    const float* det        = (const float*)d_in[0];
    const float* scores     = (const float*)d_in[1];
    const int*   cls        = (const int*)d_in[2];
    const float* emb        = (const float*)d_in[3];
    const float* memo_emb   = (const float*)d_in[4];
    const int*   memo_cls   = (const int*)d_in[5];
    const int*   memo_trk   = (const int*)d_in[6];
    const int*   num_tracks = (const int*)d_in[7];
    float* out = (float*)d_out;

    init_kernel<<<ND / 256, 256>>>();
    sort_kernel<<<1, 1024>>>(scores);
    gather_kernel<<<ND, 256>>>(det, scores, cls, emb);
    nms_kernel<<<ND / 8, 256>>>();                 // 8 warps/block, 1 warp per det
    compact_kernel<<<1, 1024>>>();
    embcompact_kernel<<<ND, 64>>>();
    sgemm_kernel<<<dim3(MM / BN, ND / BM), 256>>>(memo_emb);
    colmerge_kernel<<<MM / 256, 256>>>();
    simsrow_kernel<<<ND, 256>>>(memo_cls, out);
    greedy_kernel<<<1, 32>>>(memo_trk, num_tracks, out);
}

// round 7
// speedup vs baseline: 1.0060x; 1.0060x over previous
#include <cuda_runtime.h>
#include <math.h>

#define ND 4096
#define MM 8192
#define DE 256
#define TOPK 8

#define OBJ_THR   0.3f
#define INIT_THR  0.7f
#define MATCH_THR 0.5f
#define IOU_BACK  0.3f
#define IOU_CLASS 0.7f
#define CEXP      32.0f

#define BM 128
#define BN 128
#define BK 16
#define NSEG (ND / BM)   // 32 block-rows max

// ---------------- scratch (device globals; no allocation allowed) ----------
static __device__ float    g_feats[(size_t)ND * MM];   // stores E = exp(f - 32)
static __device__ int      g_order[ND];
static __device__ float    g_scores_s[ND];
static __device__ int      g_cls_s[ND];
static __device__ float4   g_boxes_s[ND];
static __device__ float    g_area_s[ND];
static __device__ float    g_emb_s[ND * DE];
static __device__ float    g_embc[ND * DE];            // compacted embeddings
static __device__ int      g_bad[ND];
static __device__ int      g_valid[ND];
static __device__ int      g_vpos[ND];                 // sorted row -> compact row
static __device__ int      g_nvalid;
static __device__ float    g_colpart[NSEG][MM];        // per-blockrow col sums of E
static __device__ float    g_colhalf[MM];              // 0.5 / colsum
static __device__ float    g_topv[ND][TOPK];
static __device__ int      g_topi[ND][TOPK];
static __device__ int      g_ids[ND];

// ---------------- 1. argsort(-scores) stable --------------------------------
__global__ void sort_kernel(const float* __restrict__ scores) {
    __shared__ unsigned long long keys[ND];
    int t = threadIdx.x;
    for (int i = t; i < ND; i += 1024) {
        unsigned u = __float_as_uint(scores[i]);
        u ^= (u & 0x80000000u) ? 0xFFFFFFFFu : 0x80000000u;
        u = ~u;                                              // descending score
        keys[i] = ((unsigned long long)u << 32) | (unsigned)i;
    }
    __syncthreads();
    for (int k = 2; k <= ND; k <<= 1) {
        for (int j = k >> 1; j > 0; j >>= 1) {
            for (int i = t; i < ND; i += 1024) {
                int ixj = i ^ j;
                if (ixj > i) {
                    bool up = ((i & k) == 0);
                    unsigned long long a = keys[i], b = keys[ixj];
                    bool sw = up ? (a > b) : (a < b);
                    if (sw) { keys[i] = b; keys[ixj] = a; }
                }
            }
            __syncthreads();
        }
    }
    for (int i = t; i < ND; i += 1024)
        g_order[i] = (int)(keys[i] & 0xFFFFFFFFu);
}

// ---------------- 2. gather sorted views (+ areas) ---------------------------
__global__ void gather_kernel(const float* __restrict__ det,
                              const float* __restrict__ scores,
                              const int*   __restrict__ cls,
                              const float* __restrict__ emb) {
    int i = blockIdx.x;
    int o = g_order[i];
    if (threadIdx.x == 0) {
        g_scores_s[i] = scores[o];
        g_cls_s[i]    = cls[o];
        float4 b;
        b.x = det[o * 4 + 0]; b.y = det[o * 4 + 1];
        b.z = det[o * 4 + 2]; b.w = det[o * 4 + 3];
        g_boxes_s[i] = b;
        g_area_s[i] = fmaxf(b.z - b.x, 0.f) * fmaxf(b.w - b.y, 0.f);
    }
    for (int k = threadIdx.x; k < DE; k += blockDim.x)
        g_emb_s[i * DE + k] = emb[o * DE + k];
}

// ---------------- 3. NMS: warp per detection, 128 j's per ballot ------------
__global__ void nms_kernel() {
    int i = (blockIdx.x * blockDim.x + threadIdx.x) >> 5;   // 4096 warps
    int lane = threadIdx.x & 31;
    float4 bx = g_boxes_s[i];
    float  si = g_scores_s[i];
    float  thr = (si < OBJ_THR) ? IOU_BACK : IOU_CLASS;
    float  area_i = g_area_s[i];
    bool bad = false;
    for (int j0 = 0; j0 < i; j0 += 128) {
        bool ex = false;
#pragma unroll
        for (int u = 0; u < 4; u++) {
            int j = j0 + u * 32 + lane;
            if (j < i) {
                float4 bb = g_boxes_s[j];
                float  aj = g_area_s[j];
                float lx = fmaxf(bx.x, bb.x), ly = fmaxf(bx.y, bb.y);
                float rx = fminf(bx.z, bb.z), ry = fminf(bx.w, bb.w);
                float w = fmaxf(rx - lx, 0.f), h = fmaxf(ry - ly, 0.f);
                float inter = w * h;
                float denom = fmaxf(area_i + aj - inter, 1e-6f);
                ex |= (inter / denom > thr);   // exact division (reference semantics)
            }
        }
        if (__any_sync(0xFFFFFFFFu, ex)) { bad = true; break; }
    }
    if (lane == 0) g_bad[i] = bad ? 1 : 0;
}

// ---------------- 4. compaction (prefix sum over valid) ---------------------
__global__ void compact_kernel() {
    __shared__ int s[1024];
    int t = threadIdx.x;
    int v[4], cnt = 0;
#pragma unroll
    for (int k = 0; k < 4; k++) {
        v[k] = g_bad[t * 4 + k] ? 0 : 1;
        cnt += v[k];
    }
    s[t] = cnt;
    __syncthreads();
    for (int off = 1; off < 1024; off <<= 1) {
        int val = s[t];
        if (t >= off) val += s[t - off];
        __syncthreads();
        s[t] = val;
        __syncthreads();
    }
    int base = s[t] - cnt;
#pragma unroll
    for (int k = 0; k < 4; k++) {
        int i = t * 4 + k;
        g_valid[i] = v[k];
        g_vpos[i] = base;
        if (v[k]) base++;
    }
    if (t == 1023) g_nvalid = s[1023];
}

__global__ void embcompact_kernel() {
    int r = blockIdx.x;
    if (!g_valid[r]) return;
    int p = g_vpos[r];
    const float4* src = (const float4*)&g_emb_s[r * DE];
    float4* dst = (float4*)&g_embc[p * DE];
    dst[threadIdx.x] = src[threadIdx.x];   // 64 threads x float4 = 256 floats
}

// ------- 5. SGEMM on compacted rows; epilogue: E = exp(f-32) + col sums -----
__global__ void sgemm_kernel(const float* __restrict__ B) {
    int nv = g_nvalid;
    int bm = blockIdx.y * BM;
    if (bm >= nv) return;
    __shared__ float As[BK][BM + 4];
    __shared__ float Bs[BK][BN + 4];
    __shared__ float s_part[16][BN];      // per-threadrow column partial sums
    int bn = blockIdx.x * BN;
    int tid = threadIdx.x;   // 256
    int ti = tid / 16;       // 0..15 thread-row group
    int tr = ti * 8;
    int tc = (tid % 16) * 8;

    float acc[8][8];
#pragma unroll
    for (int i = 0; i < 8; i++)
#pragma unroll
        for (int j = 0; j < 8; j++) acc[i][j] = 0.f;

    int lrow = tid / 4;
    int lc4  = (tid % 4) * 4;

    for (int k0 = 0; k0 < DE; k0 += BK) {
        __syncthreads();
#pragma unroll
        for (int l = 0; l < 2; l++) {
            int row = l * 64 + lrow;
            float4 va = *(const float4*)&g_embc[(bm + row) * DE + k0 + lc4];
            As[lc4 + 0][row] = va.x; As[lc4 + 1][row] = va.y;
            As[lc4 + 2][row] = va.z; As[lc4 + 3][row] = va.w;
            float4 vb = *(const float4*)&B[(size_t)(bn + row) * DE + k0 + lc4];
            Bs[lc4 + 0][row] = vb.x; Bs[lc4 + 1][row] = vb.y;
            Bs[lc4 + 2][row] = vb.z; Bs[lc4 + 3][row] = vb.w;
        }
        __syncthreads();
#pragma unroll
        for (int kk = 0; kk < BK; kk++) {
            float a[8], b[8];
#pragma unroll
            for (int i = 0; i < 8; i++) a[i] = As[kk][tr + i];
#pragma unroll
            for (int j = 0; j < 8; j++) b[j] = Bs[kk][tc + j];
#pragma unroll
            for (int i = 0; i < 8; i++)
#pragma unroll
                for (int j = 0; j < 8; j++) acc[i][j] = fmaf(a[i], b[j], acc[i][j]);
        }
    }
    // E = exp(acc - 32); write feats
#pragma unroll
    for (int i = 0; i < 8; i++) {
#pragma unroll
        for (int j = 0; j < 8; j++) acc[i][j] = __expf(acc[i][j] - CEXP);
        float* dst = &g_feats[(size_t)(bm + tr + i) * MM + bn + tc];
        *(float4*)dst       = make_float4(acc[i][0], acc[i][1], acc[i][2], acc[i][3]);
        *(float4*)(dst + 4) = make_float4(acc[i][4], acc[i][5], acc[i][6], acc[i][7]);
    }
    // per-thread column partial sums (valid rows only)
#pragma unroll
    for (int j = 0; j < 8; j++) {
        float ps = 0.f;
#pragma unroll
        for (int i = 0; i < 8; i++) {
            if (bm + tr + i < nv) ps += acc[i][j];
        }
        s_part[ti][tc + j] = ps;
    }
    __syncthreads();
    // deterministic 16-way reduce per column
    if (tid < BN) {
        float s = 0.f;
#pragma unroll
        for (int k = 0; k < 16; k++) s += s_part[k][tid];
        g_colpart[blockIdx.y][bn + tid] = s;
    }
}

// ---------------- 6. merge column partials (plain sums) ---------------------
__global__ void colmerge_kernel() {
    int c = blockIdx.x * 256 + threadIdx.x;
    int nseg = (g_nvalid + BM - 1) / BM;
    float s = 0.f;
    for (int seg = 0; seg < nseg; seg++) s += g_colpart[seg][c];
    g_colhalf[c] = 0.5f / s;
}

// ---------------- 7. sims + row sum + top-8 (single pass, local top-9) ------
__global__ void simsrow_kernel(const int* __restrict__ memo_cls,
                               float* __restrict__ out) {
    __shared__ float srow[MM];
    __shared__ float s_red[256];
    __shared__ int   s_ri[256];
    __shared__ float sv[9 * 256];
    __shared__ int   si[9 * 256];
    int r = blockIdx.x, t = threadIdx.x;
    float* orow = out + 2 * ND + (size_t)r * MM;
    if (!g_valid[r]) {
        float4 z = make_float4(0.f, 0.f, 0.f, 0.f);
        float4* o4 = (float4*)orow;
        for (int j = t; j < MM / 4; j += 256) o4[j] = z;
        if (t < TOPK) { g_topv[r][t] = 0.f; g_topi[r][t] = 0; }
        return;
    }
    int v = g_vpos[r];
    const float4* f4 = (const float4*)(g_feats + (size_t)v * MM);
    float p0 = 0.f, p1 = 0.f;
#pragma unroll
    for (int it = 0; it < 8; it++) {
        int idx = t + it * 256;
        float4 x = f4[idx];
        ((float4*)srow)[idx] = x;
        p0 += x.x + x.z;
        p1 += x.y + x.w;
    }
    s_red[t] = p0 + p1;
    __syncthreads();
    for (int o = 128; o; o >>= 1) {
        if (t < o) s_red[t] += s_red[t + o];
        __syncthreads();
    }
    float hr = 0.5f / s_red[0];
    int clsr = g_cls_s[r];
    __syncthreads();

    // single pass: sims value, gmem write, local top-9 (desc, first-index ties)
    float lv[9]; int li[9];
#pragma unroll
    for (int k = 0; k < 9; k++) { lv[k] = -1.f; li[k] = MM; }
    for (int j = t; j < MM; j += 256) {
        float E = srow[j];
        float hc = g_colhalf[j];
        float x = (memo_cls[j] == clsr) ? E * (hr + hc) : 0.f;
        orow[j] = x;
        if (x > lv[8]) {
            lv[8] = x; li[8] = j;
#pragma unroll
            for (int p = 8; p > 0; p--) {
                if (lv[p] > lv[p - 1]) {     // strict: equal keeps earlier j first
                    float tv = lv[p]; lv[p] = lv[p - 1]; lv[p - 1] = tv;
                    int   tj = li[p]; li[p] = li[p - 1]; li[p - 1] = tj;
                }
            }
        }
    }
#pragma unroll
    for (int k = 0; k < 9; k++) { sv[k * 256 + t] = lv[k]; si[k * 256 + t] = li[k]; }
    __syncthreads();

    // 8 selection rounds over 256 sorted head candidates
    int h = 0;
    for (int k = 0; k < TOPK; k++) {
        float cv = (h < 9) ? sv[h * 256 + t] : -1.f;
        int   ci = (h < 9) ? si[h * 256 + t] : MM;
        s_red[t] = cv; s_ri[t] = ci;
        __syncthreads();
        for (int o = 128; o; o >>= 1) {
            if (t < o) {
                float ov = s_red[t + o]; int oi = s_ri[t + o];
                if (ov > s_red[t] || (ov == s_red[t] && oi < s_ri[t])) {
                    s_red[t] = ov; s_ri[t] = oi;
                }
            }
            __syncthreads();
        }
        float bv = s_red[0]; int bi = s_ri[0];
        if (t == 0) { g_topv[r][k] = bv; g_topi[r][k] = bi; }
        __syncthreads();
        if (cv == bv && ci == bi) h++;
    }
}

// ---------------- 8. sequential greedy + new tracks + scatter ---------------
__global__ void greedy_kernel(const int* __restrict__ memo_track,
                              const int* __restrict__ num_tracks_ptr,
                              float* __restrict__ out) {
    __shared__ float          s_tv[ND];          // 16 KB
    __shared__ unsigned short s_pk[ND];          // 8 KB: ti|valid<<13|strong<<14|init<<15
    __shared__ unsigned       tk[MM / 32];       // taken bitmask 1 KB
    int lane = threadIdx.x;
    for (int i = lane; i < MM / 32; i += 32) tk[i] = 0u;
    for (int i = lane; i < ND; i += 32) {
        float tv = g_topv[i][0];
        int   ti = g_topi[i][0];
        float sc = g_scores_s[i];
        int   vl = g_valid[i];
        s_tv[i] = tv;
        s_pk[i] = (unsigned short)(ti | (vl << 13) |
                                   ((sc > OBJ_THR) << 14) | ((sc > INIT_THR) << 15));
    }
    __syncwarp();

    const float* sims = out + 2 * ND;

    for (int c = 0; c < ND / 32; c++) {
        int r = c * 32 + lane;
        float tv = s_tv[r];
        int pk = s_pk[r];
        int ti = pk & 0x1FFF;
        bool strong = (pk >> 14) & 1;

        bool relevant = tv > MATCH_THR;
        unsigned relmask = __ballot_sync(0xFFFFFFFFu, relevant);
        bool hazard = relevant && ((tk[ti >> 5] >> (ti & 31)) & 1u);
        unsigned same = __match_any_sync(0xFFFFFFFFu, ti);
        bool dup = relevant && ((same & relmask) != (1u << lane));
        bool anyhaz = __any_sync(0xFFFFFFFFu, hazard);
        bool anydup = __any_sync(0xFFFFFFFFu, dup);

        if (!anyhaz && !anydup) {
            int idv = -1;
            bool assign = false;
            if (relevant) {
                int cur = memo_track[ti];
                bool is_track = cur > -1;
                assign = is_track && strong;
                idv = assign ? cur : ((!is_track) ? -2 : -1);
            }
            g_ids[r] = idv;
            if (assign) atomicOr(&tk[ti >> 5], 1u << (ti & 31));
            __syncwarp();
        } else {
            for (int l = 0; l < 32; l++) {
                int rr = c * 32 + l;
                float tv0 = s_tv[rr];
                if (!(tv0 > MATCH_THR)) {
                    if (lane == 0) g_ids[rr] = -1;
                    __syncwarp();
                    continue;
                }
                float conf; int ind;
                bool ok = false;
                if (lane < TOPK) {
                    int cc = g_topi[rr][lane];
                    ok = !((tk[cc >> 5] >> (cc & 31)) & 1u);
                }
                unsigned b = __ballot_sync(0xFFFFFFFFu, ok);
                if (b) {
                    int k = __ffs(b) - 1;
                    conf = g_topv[rr][k];
                    ind  = g_topi[rr][k];
                } else {
                    const float* row = sims + (size_t)rr * MM;
                    float bv = -1.f; int bi = MM;
                    for (int j = lane; j < MM; j += 32) {
                        bool tkn = (tk[j >> 5] >> (j & 31)) & 1u;
                        float x = tkn ? 0.f : row[j];
                        if (x > bv) { bv = x; bi = j; }
                    }
                    for (int off = 16; off; off >>= 1) {
                        float ov = __shfl_down_sync(0xFFFFFFFFu, bv, off);
                        int   oi = __shfl_down_sync(0xFFFFFFFFu, bi, off);
                        if (ov > bv || (ov == bv && oi < bi)) { bv = ov; bi = oi; }
                    }
                    conf = __shfl_sync(0xFFFFFFFFu, bv, 0);
                    ind  = __shfl_sync(0xFFFFFFFFu, bi, 0);
                }
                if (lane == 0) {
                    int cur = memo_track[ind];
                    bool match = conf > MATCH_THR;
                    bool is_track = cur > -1;
                    bool strong2 = (s_pk[rr] >> 14) & 1;
                    bool assign = match && is_track && strong2;
                    g_ids[rr] = assign ? cur : ((match && !is_track) ? -2 : -1);
                    if (assign) atomicOr(&tk[ind >> 5], 1u << (ind & 31));
                }
                __syncwarp();
            }
        }
    }
    __syncwarp();

    int num_tracks = *num_tracks_ptr;
    int carry = 0;
    for (int c = 0; c < ND / 32; c++) {
        int r = c * 32 + lane;
        int idv = g_ids[r];
        int pk = s_pk[r];
        int vld = (pk >> 13) & 1;
        bool newt = (idv == -1) && ((pk >> 15) & 1) && vld;
        unsigned bm = __ballot_sync(0xFFFFFFFFu, newt);
        int rank = __popc(bm & ((1u << lane) - 1u));
        if (newt) idv = num_tracks + carry + rank;
        carry += __popc(bm);
        int o = g_order[r];
        out[o] = (float)idv;
        out[ND + o] = vld ? 1.f : 0.f;
    }
}

// ---------------- launch -----------------------------------------------------
extern "C" void kernel_launch(void* const* d_in, const int* in_sizes, int n_in,
                              void* d_out, int out_size) {
    (void)in_sizes; (void)n_in; (void)out_size;
    const float* det        = (const float*)d_in[0];
    const float* scores     = (const float*)d_in[1];
    const int*   cls        = (const int*)d_in[2];
    const float* emb        = (const float*)d_in[3];
    const float* memo_emb   = (const float*)d_in[4];
    const int*   memo_cls   = (const int*)d_in[5];
    const int*   memo_trk   = (const int*)d_in[6];
    const int*   num_tracks = (const int*)d_in[7];
    float* out = (float*)d_out;

    sort_kernel<<<1, 1024>>>(scores);
    gather_kernel<<<ND, 256>>>(det, scores, cls, emb);
    nms_kernel<<<ND / 8, 256>>>();                 // 8 warps/block, 1 warp per det
    compact_kernel<<<1, 1024>>>();
    embcompact_kernel<<<ND, 64>>>();
    sgemm_kernel<<<dim3(MM / BN, ND / BM), 256>>>(memo_emb);
    colmerge_kernel<<<MM / 256, 256>>>();
    simsrow_kernel<<<ND, 256>>>(memo_cls, out);
    greedy_kernel<<<1, 32>>>(memo_trk, num_tracks, out);
}